// round 6
// baseline (speedup 1.0000x reference)
#include <cuda_runtime.h>
#include <math.h>

// Static problem sizes (fixed by the reference setup_inputs)
#define Bv   32
#define Cc   512
#define Nn   64
#define NN   4096          // N*N
#define Ss   128
#define Mm   256
#define Pp   2080          // upper-tri proposals
#define BPj  (Bv * Pp)     // 66560
#define INV_T 10.0f        // 1/0.1

// ---------------- device scratch (static; no allocations) ----------------
__device__ float g_G[(size_t)BPj * Cc];   // gathered raw video feats, (BP, C) row-major
__device__ float g_invn[BPj];             // 1/||v[b,p]||
__device__ float g_sents_n[Ss * Cc];      // normalized sentences (S,C)
__device__ float g_sents_nT[Cc * Ss];     // transposed copy (C,S)
__device__ int   g_postab[Pp];            // proposal p -> flat pos r*64+c
__device__ int   g_bestj[Mm];             // per-moment best (b*P+p)
__device__ float g_posscore[Mm];          // inter_video_pos[m]
__device__ float g_qsum[Ss];              // inter-query masked exp sums per sentence
__device__ float g_liv;                   // inter-video loss sum accumulator

// ---------------- f32x2 packed-FMA helpers (FFMA2, not emitted by ptxas) ----
__device__ __forceinline__ unsigned long long dup2(float x) {
    unsigned long long r; asm("mov.b64 %0, {%1, %1};" : "=l"(r) : "f"(x)); return r;
}
__device__ __forceinline__ unsigned long long pk2(float x, float y) {
    unsigned long long r; asm("mov.b64 %0, {%1, %2};" : "=l"(r) : "f"(x), "f"(y)); return r;
}
__device__ __forceinline__ void ffma2(unsigned long long& d, unsigned long long a, unsigned long long b) {
    asm("fma.rn.f32x2 %0, %1, %2, %0;" : "+l"(d) : "l"(a), "l"(b));
}
__device__ __forceinline__ void upk(unsigned long long v, float& lo, float& hi) {
    asm("mov.b64 {%0, %1}, %2;" : "=f"(lo), "=f"(hi) : "l"(v));
}

// ---------------- init: proposal table + zero accumulators ----------------
__global__ void k_init() {
    int tid = blockIdx.x * 256 + threadIdx.x;
    if (tid < NN) {
        int r = tid >> 6, c = tid & 63;
        if (c >= r) {
            int p = r * Nn - (r * (r - 1)) / 2 + (c - r);
            g_postab[p] = tid;
        }
    }
    if (tid < Ss) g_qsum[tid] = 0.f;
    if (tid == 0) g_liv = 0.f;
}

// ---------------- normalize sentences ----------------
__global__ void k_sents(const float* __restrict__ sf) {
    int s = blockIdx.x, t = threadIdx.x;   // 128 threads
    __shared__ float red[128];
    __shared__ float sinv;
    float v[4]; float acc = 0.f;
#pragma unroll
    for (int q = 0; q < 4; q++) { v[q] = sf[s * Cc + t + 128 * q]; acc += v[q] * v[q]; }
    red[t] = acc; __syncthreads();
    for (int off = 64; off > 0; off >>= 1) { if (t < off) red[t] += red[t + off]; __syncthreads(); }
    if (t == 0) sinv = 1.f / fmaxf(sqrtf(red[0]), 1e-12f);
    __syncthreads();
    float iv = sinv;
#pragma unroll
    for (int q = 0; q < 4; q++) {
        int c = t + 128 * q; float y = v[q] * iv;
        g_sents_n[s * Cc + c] = y;
        g_sents_nT[c * Ss + s] = y;
    }
}

// -------- fused gather + per-proposal norm (32 proposals x 512 channels) ----
// dynamic smem: 32 rows x 516 floats (padded) = 66048 bytes
#define GPAD 516
__global__ void k_gathern(const float* __restrict__ vf) {
    extern __shared__ float smg[];
    int b = blockIdx.y;
    int p0 = blockIdx.x * 32;              // Pp = 65*32 exact
    int t = threadIdx.x;                   // 256 threads
    int pl = t & 31, cq = t >> 5;          // warp-over-proposals: 128B coalesced
    int pos = __ldg(&g_postab[p0 + pl]);
    const float* src = vf + (size_t)b * ((size_t)Cc * NN) + pos;
#pragma unroll 8
    for (int i = 0; i < 64; i++) {
        int c = cq + 8 * i;
        smg[pl * GPAD + c] = __ldg(&src[(size_t)c * NN]);
    }
    __syncthreads();
    // norms: 8 warps x 4 rows
    int w = t >> 5, lane = t & 31;
#pragma unroll
    for (int rr = 0; rr < 4; rr++) {
        int row = w * 4 + rr;
        float s = 0.f;
#pragma unroll
        for (int q = 0; q < 16; q++) { float v = smg[row * GPAD + lane + 32 * q]; s += v * v; }
#pragma unroll
        for (int off = 16; off > 0; off >>= 1) s += __shfl_xor_sync(0xffffffffu, s, off);
        if (lane == 0) g_invn[b * Pp + p0 + row] = 1.f / fmaxf(sqrtf(s), 1e-12f);
    }
    // write compact rows (coalesced float4)
    size_t j0 = (size_t)b * Pp + p0;
    for (int idx = t; idx < 32 * 128; idx += 256) {
        int row = idx >> 7, c4 = idx & 127;
        *(float4*)&g_G[(j0 + row) * Cc + c4 * 4] = *(const float4*)&smg[row * GPAD + c4 * 4];
    }
}

// ---------------- argmax of iou2ds over valid proposals (top-1) ----------------
__global__ void k_topk(const float* __restrict__ iou2ds) {
    int m = blockIdx.x, t = threadIdx.x;   // 256 threads
    __shared__ float sv[256]; __shared__ int si[256];
    float bv = -1e30f; int bi = 0;
    for (int p = t; p < Pp; p += 256) {
        float v = iou2ds[(size_t)m * NN + g_postab[p]];
        if (v > bv) { bv = v; bi = p; }     // ascending scan keeps first on ties
    }
    sv[t] = bv; si[t] = bi; __syncthreads();
    for (int off = 128; off > 0; off >>= 1) {
        if (t < off) {
            float v2 = sv[t + off]; int i2 = si[t + off];
            if (v2 > sv[t] || (v2 == sv[t] && i2 < si[t])) { sv[t] = v2; si[t] = i2; }
        }
        __syncthreads();
    }
    if (t == 0) g_bestj[m] = (m >> 3) * Pp + si[0];
}

// ---- big GEMM (128 x 66560 x 512) via FFMA2, fused with masked exp-sum ----
// Block: 128 s x 128 j tile, BK=32, 256 threads, 8x8 register tile (j packed).
__global__ __launch_bounds__(256, 2) void k_gemm(const float* __restrict__ iou2d) {
    __shared__ float As[32][132];
    __shared__ float Bs[32][132];
    int t = threadIdx.x;
    int j0 = blockIdx.x * 128;
    int tx = t & 15, ty = t >> 4;
    unsigned long long acc2[8][4];
#pragma unroll
    for (int i = 0; i < 8; i++)
#pragma unroll
        for (int j = 0; j < 4; j++) acc2[i][j] = 0ull;  // (0.0f, 0.0f)

    int arow = t >> 1;
    int kb = (t & 1) * 16;

    for (int k0 = 0; k0 < Cc; k0 += 32) {
#pragma unroll
        for (int u = 0; u < 4; u++) {
            int kk = kb + u * 4;
            float4 av = *(const float4*)(g_sents_n + arow * Cc + k0 + kk);
            As[kk + 0][arow] = av.x; As[kk + 1][arow] = av.y;
            As[kk + 2][arow] = av.z; As[kk + 3][arow] = av.w;
            float4 bv = *(const float4*)(g_G + (size_t)(j0 + arow) * Cc + k0 + kk);
            Bs[kk + 0][arow] = bv.x; Bs[kk + 1][arow] = bv.y;
            Bs[kk + 2][arow] = bv.z; Bs[kk + 3][arow] = bv.w;
        }
        __syncthreads();
#pragma unroll
        for (int k = 0; k < 32; k++) {
            float4 a0 = *(const float4*)&As[k][ty * 8];
            float4 a1 = *(const float4*)&As[k][ty * 8 + 4];
            float4 b0 = *(const float4*)&Bs[k][tx * 8];
            float4 b1 = *(const float4*)&Bs[k][tx * 8 + 4];
            unsigned long long b2[4];
            b2[0] = pk2(b0.x, b0.y); b2[1] = pk2(b0.z, b0.w);
            b2[2] = pk2(b1.x, b1.y); b2[3] = pk2(b1.z, b1.w);
            unsigned long long a2[8];
            a2[0] = dup2(a0.x); a2[1] = dup2(a0.y); a2[2] = dup2(a0.z); a2[3] = dup2(a0.w);
            a2[4] = dup2(a1.x); a2[5] = dup2(a1.y); a2[6] = dup2(a1.z); a2[7] = dup2(a1.w);
#pragma unroll
            for (int i = 0; i < 8; i++)
#pragma unroll
                for (int j = 0; j < 4; j++)
                    ffma2(acc2[i][j], a2[i], b2[j]);
        }
        __syncthreads();
    }

    // unpack accumulators
    float acc[8][8];
#pragma unroll
    for (int i = 0; i < 8; i++)
#pragma unroll
        for (int jp = 0; jp < 4; jp++)
            upk(acc2[i][jp], acc[i][2 * jp], acc[i][2 * jp + 1]);

    // epilogue: score = acc * inv_norm[j]; accumulate exp(score/t) under neg mask
    float rowsum[8];
#pragma unroll
    for (int i = 0; i < 8; i++) rowsum[i] = 0.f;
#pragma unroll
    for (int jj = 0; jj < 8; jj++) {
        int j = j0 + tx * 8 + jj;
        int b = j / Pp;
        int p = j - b * Pp;
        float inv = g_invn[j];
        int pos = g_postab[p];
#pragma unroll
        for (int i = 0; i < 8; i++) {
            int s = ty * 8 + i;
            float e = __expf(acc[i][jj] * inv * INV_T);
            bool neg = true;
            if ((s >> 2) == b) {                       // own video: check IoU
                if (iou2d[(size_t)s * NN + pos] > 0.5f) neg = false;
            }
            if (neg) rowsum[i] += e;
        }
    }
    // reduce across the 16 tx lanes of each half-warp, then one atomic per s
#pragma unroll
    for (int i = 0; i < 8; i++) {
        float v = rowsum[i];
#pragma unroll
        for (int off = 8; off > 0; off >>= 1) v += __shfl_xor_sync(0xffffffffu, v, off);
        if (tx == 0) atomicAdd(&g_qsum[ty * 8 + i], v);
    }
}

// ---------------- inter-video loss: per moment, dots vs all 128 sentences -----
__global__ void k_iv() {
    int m = blockIdx.x, s = threadIdx.x;   // 128 threads, thread = sentence
    __shared__ float tv[512];
    __shared__ float red[128];
    __shared__ float posv;
    int j = g_bestj[m];
    float inm = g_invn[j];
    const float* gr = g_G + (size_t)j * Cc;
#pragma unroll
    for (int q = 0; q < 4; q++) tv[s + 128 * q] = gr[s + 128 * q] * inm;
    __syncthreads();
    float d0 = 0, d1 = 0, d2 = 0, d3 = 0;
#pragma unroll 4
    for (int c = 0; c < Cc; c += 4) {
        d0 += tv[c]     * g_sents_nT[(c)     * Ss + s];
        d1 += tv[c + 1] * g_sents_nT[(c + 1) * Ss + s];
        d2 += tv[c + 2] * g_sents_nT[(c + 2) * Ss + s];
        d3 += tv[c + 3] * g_sents_nT[(c + 3) * Ss + s];
    }
    float dot = (d0 + d1) + (d2 + d3);
    int sp = m >> 1;
    if (s == sp) posv = dot;               // pos score = all[m, m/2]
    red[s] = (s == sp) ? 0.f : __expf(dot * INV_T);
    __syncthreads();
    for (int off = 64; off > 0; off >>= 1) { if (s < off) red[s] += red[s + off]; __syncthreads(); }
    if (s == 0) {
        float pos = posv;
        float liv = -(pos * INV_T - logf(__expf(pos * INV_T) + red[0]));
        atomicAdd(&g_liv, liv);
        g_posscore[m] = pos;
    }
}

// ---------------- final: inter-query loss + means + total ----------------
__global__ void k_final(float* __restrict__ out, int out_size) {
    int t = threadIdx.x;   // 256
    __shared__ float red[256];
    float ps = g_posscore[t];
    float q = g_qsum[t >> 1];
    float liq = -(ps * INV_T - logf(__expf(ps * INV_T) + q));
    red[t] = liq; __syncthreads();
    for (int off = 128; off > 0; off >>= 1) { if (t < off) red[t] += red[t + off]; __syncthreads(); }
    if (t == 0) {
        float liq_m = red[0] / (float)Mm;
        float liv_m = g_liv / (float)Mm;
        if (out_size > 0) out[0] = liv_m + liq_m;
        if (out_size > 1) out[1] = liv_m;
        if (out_size > 2) out[2] = liq_m;
    }
}

// ---------------- launch ----------------
extern "C" void kernel_launch(void* const* d_in, const int* in_sizes, int n_in,
                              void* d_out, int out_size) {
    const float* vf     = (const float*)d_in[0];  // video_feats (B,C,N,N)
    const float* sf     = (const float*)d_in[1];  // sents_feats (S,C)
    const float* iou2d  = (const float*)d_in[4];  // (S,N,N)
    const float* iou2ds = (const float*)d_in[5];  // (M,N,N)
    float* out = (float*)d_out;

    const int gsmem = 32 * GPAD * 4;  // 66048 bytes
    cudaFuncSetAttribute(k_gathern, cudaFuncAttributeMaxDynamicSharedMemorySize, gsmem);

    k_init   <<<16, 256>>>();
    k_sents  <<<Ss, 128>>>(sf);
    k_gathern<<<dim3(Pp / 32, Bv), 256, gsmem>>>(vf);
    k_topk   <<<Mm, 256>>>(iou2ds);
    k_gemm   <<<BPj / 128, 256>>>(iou2d);
    k_iv     <<<Mm, 128>>>();
    k_final  <<<1, 256>>>(out, out_size);
}

// round 9
// speedup vs baseline: 2.2662x; 2.2662x over previous
#include <cuda_runtime.h>
#include <cuda_bf16.h>
#include <math.h>
#include <stdint.h>

// Static problem sizes (fixed by the reference setup_inputs)
#define Bv   32
#define Nn   64
#define NN   4096          // N*N
#define Ss   128
#define Mm   256
#define Pp   2080          // upper-tri proposals
#define BPj  (Bv * Pp)     // 66560
#define Cc   512
#define INV_T 10.0f        // 1/0.1

// ---------------- device scratch (static; no allocations) ----------------
__device__ __nv_bfloat16 g_Gbf[(size_t)BPj * Cc]; // gathered video feats bf16 (BP,C) ~68MB
__device__ __nv_bfloat16 g_sents_bf[Ss * Cc];     // normalized sentences bf16 (S,C)
__device__ float g_invn[BPj];             // 1/||v[b,p]|| (fp32 norms)
__device__ float g_sents_nT[Cc * Ss];     // normalized sentences transposed (C,S) fp32
__device__ int   g_postab[Pp];            // proposal p -> flat pos r*64+c
__device__ int   g_bestj[Mm];             // per-moment best (b*P+p)
__device__ float g_posscore[Mm];          // inter_video_pos[m]
__device__ float g_qsum[Ss];              // inter-query masked exp sums per sentence
__device__ float g_liv;                   // inter-video loss sum accumulator

// ---------------- mma helpers (baseline PTX, sm_80+) ----------------
__device__ __forceinline__ uint32_t smem_u32(const void* p) {
    uint32_t a;
    asm("{ .reg .u64 t; cvta.to.shared.u64 t, %1; cvt.u32.u64 %0, t; }" : "=r"(a) : "l"(p));
    return a;
}
__device__ __forceinline__ void ldsm4(uint32_t* r, uint32_t addr) {
    asm volatile("ldmatrix.sync.aligned.m8n8.x4.shared.b16 {%0,%1,%2,%3}, [%4];"
                 : "=r"(r[0]), "=r"(r[1]), "=r"(r[2]), "=r"(r[3]) : "r"(addr));
}
__device__ __forceinline__ void mma16816(float* d, const uint32_t* a, uint32_t b0, uint32_t b1) {
    asm volatile("mma.sync.aligned.m16n8k16.row.col.f32.bf16.bf16.f32 "
                 "{%0,%1,%2,%3}, {%4,%5,%6,%7}, {%8,%9}, {%0,%1,%2,%3};"
                 : "+f"(d[0]), "+f"(d[1]), "+f"(d[2]), "+f"(d[3])
                 : "r"(a[0]), "r"(a[1]), "r"(a[2]), "r"(a[3]), "r"(b0), "r"(b1));
}
__device__ __forceinline__ uint32_t bf2(float lo, float hi) {
    __nv_bfloat162 h = __float22bfloat162_rn(make_float2(lo, hi));
    return *(uint32_t*)&h;
}

// ---------------- init: proposal table + zero accumulators ----------------
__global__ void k_init() {
    int tid = blockIdx.x * 256 + threadIdx.x;
    if (tid < NN) {
        int r = tid >> 6, c = tid & 63;
        if (c >= r) {
            int p = r * Nn - (r * (r - 1)) / 2 + (c - r);
            g_postab[p] = tid;
        }
    }
    if (tid < Ss) g_qsum[tid] = 0.f;
    if (tid == 0) g_liv = 0.f;
}

// ---------------- normalize sentences (fp32 transpose + bf16 row-major) -----
__global__ void k_sents(const float* __restrict__ sf) {
    int s = blockIdx.x, t = threadIdx.x;   // 128 threads
    __shared__ float red[128];
    __shared__ float sinv;
    float v[4]; float acc = 0.f;
#pragma unroll
    for (int q = 0; q < 4; q++) { v[q] = sf[s * Cc + t + 128 * q]; acc += v[q] * v[q]; }
    red[t] = acc; __syncthreads();
    for (int off = 64; off > 0; off >>= 1) { if (t < off) red[t] += red[t + off]; __syncthreads(); }
    if (t == 0) sinv = 1.f / fmaxf(sqrtf(red[0]), 1e-12f);
    __syncthreads();
    float iv = sinv;
#pragma unroll
    for (int q = 0; q < 4; q++) {
        int c = t + 128 * q; float y = v[q] * iv;
        g_sents_bf[s * Cc + c] = __float2bfloat16(y);
        g_sents_nT[c * Ss + s] = y;
    }
}

// -------- fused gather + per-proposal norm; stores bf16 (32 props x 512 ch) --
#define GPAD 516
__global__ void k_gathern(const float* __restrict__ vf) {
    extern __shared__ float smg[];
    int b = blockIdx.y;
    int p0 = blockIdx.x * 32;              // Pp = 65*32 exact
    int t = threadIdx.x;                   // 256 threads
    int pl = t & 31, cq = t >> 5;          // warp-over-proposals: 128B coalesced
    int pos = __ldg(&g_postab[p0 + pl]);
    const float* src = vf + (size_t)b * ((size_t)Cc * NN) + pos;
#pragma unroll 8
    for (int i = 0; i < 64; i++) {
        int c = cq + 8 * i;
        smg[pl * GPAD + c] = __ldg(&src[(size_t)c * NN]);
    }
    __syncthreads();
    // norms (fp32): 8 warps x 4 rows
    int w = t >> 5, lane = t & 31;
#pragma unroll
    for (int rr = 0; rr < 4; rr++) {
        int row = w * 4 + rr;
        float s = 0.f;
#pragma unroll
        for (int q = 0; q < 16; q++) { float v = smg[row * GPAD + lane + 32 * q]; s += v * v; }
#pragma unroll
        for (int off = 16; off > 0; off >>= 1) s += __shfl_xor_sync(0xffffffffu, s, off);
        if (lane == 0) g_invn[b * Pp + p0 + row] = 1.f / fmaxf(sqrtf(s), 1e-12f);
    }
    // write compact bf16 rows (coalesced uint4 = 8 bf16)
    size_t j0 = (size_t)b * Pp + p0;
    for (int idx = t; idx < 32 * 64; idx += 256) {
        int row = idx >> 6, g = idx & 63;
        const float* p = &smg[row * GPAD + g * 8];
        uint4 u;
        u.x = bf2(p[0], p[1]); u.y = bf2(p[2], p[3]);
        u.z = bf2(p[4], p[5]); u.w = bf2(p[6], p[7]);
        *(uint4*)&g_Gbf[(j0 + row) * Cc + g * 8] = u;
    }
}

// ------- argmax of iou2ds: coalesced full-4096 scan, triu mask inline -------
__global__ void k_topk(const float* __restrict__ iou2ds) {
    int m = blockIdx.x, t = threadIdx.x;   // 256 threads
    __shared__ float sv[256]; __shared__ int si[256];
    float bv = -1e30f; int bflat = 1 << 30;
    for (int i = t; i < NN; i += 256) {
        int r = i >> 6, c = i & 63;
        if (c < r) continue;
        float v = iou2ds[(size_t)m * NN + i];
        if (v > bv) { bv = v; bflat = i; }   // ascending i keeps first on ties
    }
    sv[t] = bv; si[t] = bflat; __syncthreads();
    for (int off = 128; off > 0; off >>= 1) {
        if (t < off) {
            float v2 = sv[t + off]; int i2 = si[t + off];
            if (v2 > sv[t] || (v2 == sv[t] && i2 < si[t])) { sv[t] = v2; si[t] = i2; }
        }
        __syncthreads();
    }
    if (t == 0) {
        int i = si[0], r = i >> 6, c = i & 63;
        int p = r * Nn - (r * (r - 1)) / 2 + (c - r);
        g_bestj[m] = (m >> 3) * Pp + p;
    }
}

// ---- bf16 mma.sync GEMM (128 x 66560 x 512) fused with masked exp-sum ------
// CTA: 128 s x 128 j, BK=64, 8 warps (2m x 4n), warp tile 64x32 (4x4 m16n8k16).
__global__ __launch_bounds__(256, 2) void k_gemm(const float* __restrict__ iou2d) {
    __shared__ __align__(16) __nv_bfloat16 sA[128][72];
    __shared__ __align__(16) __nv_bfloat16 sB[128][72];
    __shared__ float sq[128];
    int t = threadIdx.x, l = t & 31, wid = t >> 5;
    int wm = wid >> 2, wn = wid & 3;
    int j0 = blockIdx.x * 128;

    float acc[4][4][4];
#pragma unroll
    for (int mt = 0; mt < 4; mt++)
#pragma unroll
        for (int nt = 0; nt < 4; nt++)
#pragma unroll
            for (int e = 0; e < 4; e++) acc[mt][nt][e] = 0.f;
    if (t < 128) sq[t] = 0.f;

    // per-thread load coords: idx = i*256+t -> row=idx>>3, group g=idx&7 (8 bf16)
    int lrow = t >> 3, lg = t & 7;

    uint4 pb[4];   // prefetched B chunk
#pragma unroll
    for (int i = 0; i < 4; i++)
        pb[i] = *(const uint4*)&g_Gbf[(size_t)(j0 + lrow + i * 32) * Cc + lg * 8];

    for (int c = 0; c < 8; c++) {
        // store prefetched B, load A (L2-resident after first wave)
#pragma unroll
        for (int i = 0; i < 4; i++) {
            *(uint4*)&sB[lrow + i * 32][lg * 8] = pb[i];
            *(uint4*)&sA[lrow + i * 32][lg * 8] =
                *(const uint4*)&g_sents_bf[(lrow + i * 32) * Cc + c * 64 + lg * 8];
        }
        __syncthreads();
        if (c < 7) {
#pragma unroll
            for (int i = 0; i < 4; i++)
                pb[i] = *(const uint4*)&g_Gbf[(size_t)(j0 + lrow + i * 32) * Cc + (c + 1) * 64 + lg * 8];
        }
#pragma unroll
        for (int ks = 0; ks < 4; ks++) {
            int k0 = ks * 16;
            uint32_t af[4][4], bfr[2][4];
#pragma unroll
            for (int mt = 0; mt < 4; mt++)
                ldsm4(af[mt], smem_u32(&sA[wm * 64 + mt * 16 + (l & 7) + ((l >> 3) & 1) * 8][k0 + (l >> 4) * 8]));
#pragma unroll
            for (int h = 0; h < 2; h++)
                ldsm4(bfr[h], smem_u32(&sB[wn * 32 + h * 16 + (l & 7) + ((l >> 3) & 1) * 8][k0 + (l >> 4) * 8]));
#pragma unroll
            for (int mt = 0; mt < 4; mt++)
#pragma unroll
                for (int nt = 0; nt < 4; nt++)
                    mma16816(acc[mt][nt], af[mt], bfr[nt >> 1][nt & 1], bfr[nt >> 1][2 + (nt & 1)]);
        }
        __syncthreads();
    }

    // ---- epilogue: masked exp-sum per sentence ----
    int vb0 = j0 / Pp;
    int bound = (vb0 + 1) * Pp;
#pragma unroll
    for (int mt = 0; mt < 4; mt++) {
#pragma unroll
        for (int h2 = 0; h2 < 2; h2++) {
            int s = wm * 64 + mt * 16 + (l >> 2) + h2 * 8;
            int myb = s >> 2;
            float sum = 0.f;
#pragma unroll
            for (int nt = 0; nt < 4; nt++) {
#pragma unroll
                for (int jj = 0; jj < 2; jj++) {
                    int j = j0 + wn * 32 + nt * 8 + (l & 3) * 2 + jj;
                    int b = (j < bound) ? vb0 : vb0 + 1;
                    float sc = acc[mt][nt][h2 * 2 + jj] * g_invn[j] * INV_T;
                    float e = __expf(sc);
                    bool add = true;
                    if (myb == b) {
                        int p = j - b * Pp;
                        if (iou2d[(size_t)s * NN + g_postab[p]] > 0.5f) add = false;
                    }
                    if (add) sum += e;
                }
            }
            sum += __shfl_xor_sync(0xffffffffu, sum, 1);
            sum += __shfl_xor_sync(0xffffffffu, sum, 2);
            if ((l & 3) == 0) atomicAdd(&sq[s], sum);
        }
    }
    __syncthreads();
    if (t < 128) atomicAdd(&g_qsum[t], sq[t]);
}

// ---------------- inter-video loss: per moment, dots vs all 128 sentences ----
__global__ void k_iv() {
    int m = blockIdx.x, s = threadIdx.x;   // 128 threads, thread = sentence
    __shared__ float tv[512];
    __shared__ float red[128];
    __shared__ float posv;
    int j = g_bestj[m];
    float inm = g_invn[j];
    const __nv_bfloat16* gr = g_Gbf + (size_t)j * Cc;
#pragma unroll
    for (int q = 0; q < 4; q++) tv[s + 128 * q] = __bfloat162float(gr[s + 128 * q]) * inm;
    __syncthreads();
    float d0 = 0, d1 = 0, d2 = 0, d3 = 0;
#pragma unroll 4
    for (int c = 0; c < Cc; c += 4) {
        d0 += tv[c]     * g_sents_nT[(c)     * Ss + s];
        d1 += tv[c + 1] * g_sents_nT[(c + 1) * Ss + s];
        d2 += tv[c + 2] * g_sents_nT[(c + 2) * Ss + s];
        d3 += tv[c + 3] * g_sents_nT[(c + 3) * Ss + s];
    }
    float dot = (d0 + d1) + (d2 + d3);
    int sp = m >> 1;
    if (s == sp) posv = dot;               // pos score = all[m, m/2]
    red[s] = (s == sp) ? 0.f : __expf(dot * INV_T);
    __syncthreads();
    for (int off = 64; off > 0; off >>= 1) { if (s < off) red[s] += red[s + off]; __syncthreads(); }
    if (s == 0) {
        float pos = posv;
        float liv = -(pos * INV_T - logf(__expf(pos * INV_T) + red[0]));
        atomicAdd(&g_liv, liv);
        g_posscore[m] = pos;
    }
}

// ---------------- final: inter-query loss + means + total ----------------
__global__ void k_final(float* __restrict__ out, int out_size) {
    int t = threadIdx.x;   // 256
    __shared__ float red[256];
    float ps = g_posscore[t];
    float q = g_qsum[t >> 1];
    float liq = -(ps * INV_T - logf(__expf(ps * INV_T) + q));
    red[t] = liq; __syncthreads();
    for (int off = 128; off > 0; off >>= 1) { if (t < off) red[t] += red[t + off]; __syncthreads(); }
    if (t == 0) {
        float liq_m = red[0] / (float)Mm;
        float liv_m = g_liv / (float)Mm;
        if (out_size > 0) out[0] = liv_m + liq_m;
        if (out_size > 1) out[1] = liv_m;
        if (out_size > 2) out[2] = liq_m;
    }
}

// ---------------- launch ----------------
extern "C" void kernel_launch(void* const* d_in, const int* in_sizes, int n_in,
                              void* d_out, int out_size) {
    const float* vf     = (const float*)d_in[0];  // video_feats (B,C,N,N)
    const float* sf     = (const float*)d_in[1];  // sents_feats (S,C)
    const float* iou2d  = (const float*)d_in[4];  // (S,N,N)
    const float* iou2ds = (const float*)d_in[5];  // (M,N,N)
    float* out = (float*)d_out;

    const int gsmem = 32 * GPAD * 4;  // 66048 B
    cudaFuncSetAttribute(k_gathern, cudaFuncAttributeMaxDynamicSharedMemorySize, gsmem);

    k_init   <<<16, 256>>>();
    k_sents  <<<Ss, 128>>>(sf);
    k_gathern<<<dim3(Pp / 32, Bv), 256, gsmem>>>(vf);
    k_topk   <<<Mm, 256>>>(iou2ds);
    k_gemm   <<<BPj / 128, 256>>>(iou2d);
    k_iv     <<<Mm, 128>>>();
    k_final  <<<1, 256>>>(out, out_size);
}